// round 2
// baseline (speedup 1.0000x reference)
#include <cuda_runtime.h>
#include <cstdint>

// Problem constants
#define NN   8192
#define NP1  8193
#define AB   16384ULL                    // A_low base (floats): after conc_low|conc_up
#define MM   67125249ULL                 // NP1*NP1
#define LR0  134258689ULL                // A_up last-row start = AB + MM + NN*NP1
#define T_TOT 134266882ULL               // total output floats = 2*NN + 2*MM
#define NVEC_FULL 33566720ULL            // number of fully-in-range float4s (floats T-2,T-1 excluded)

#define THREADS 256
#define VEC_PER_THREAD 32
#define CHUNK_F (THREADS * VEC_PER_THREAD * 4)   // 32768 floats = 128 KB per block

// Single fused kernel:
//   Phase 1: each block zero-fills its own contiguous 128KB chunk with STG.128.
//   Phase 2 (after __syncthreads, same block => ordered): patch nonzeros that
//   fall inside this chunk: conc vectors, matrix diagonals, A_up last row.
__global__ void __launch_bounds__(THREADS) relu_relax_fused(
        const float* __restrict__ lower,
        const float* __restrict__ upper,
        const float* __restrict__ alphas,
        float* __restrict__ out) {
    const int tid = threadIdx.x;
    const size_t s = (size_t)blockIdx.x * (size_t)CHUNK_F;
    const size_t e = (s + CHUNK_F < T_TOT) ? (s + CHUNK_F) : T_TOT;

    // ---------------- Phase 1: bulk zero (vectorized) ----------------
    float4* __restrict__ ov = reinterpret_cast<float4*>(out);
    const float4 z = make_float4(0.f, 0.f, 0.f, 0.f);
    const size_t v0 = (s >> 2) + (size_t)tid;

    if (blockIdx.x + 1 < gridDim.x) {
        // full chunk, unguarded
        #pragma unroll
        for (int j = 0; j < VEC_PER_THREAD; j++)
            ov[v0 + (size_t)j * THREADS] = z;
    } else {
        // tail chunk: guard; the final 2 floats (T-2, T-1) are written by
        // the last-row patch below, never by the vector path.
        #pragma unroll
        for (int j = 0; j < VEC_PER_THREAD; j++) {
            const size_t v = v0 + (size_t)j * THREADS;
            if (v < NVEC_FULL) ov[v] = z;
        }
    }

    __syncthreads();  // orders this block's zero stores before its patches

    // ---------------- Phase 2: patch nonzeros inside [s, e) ----------------

    // (a) conc_low / conc_up head vectors: floats [0, 2*NN)
    if (s < 2ULL * NN) {
        const size_t lim = (e < 2ULL * NN) ? e : (size_t)(2ULL * NN);
        for (size_t idx = s + tid; idx < lim; idx += THREADS) {
            const int i = (int)(idx & (NN - 1));
            const float l = lower[i];
            const float u = upper[i];
            float val;
            if (idx < (size_t)NN) {
                const float a = fminf(fmaxf(alphas[i], 0.f), 1.f);
                const bool active   = (u > 0.f) && (l >= 0.f);
                const bool unstable = (u > 0.f) && (l < 0.f);
                val = active ? l : (unstable ? a * l : 0.f);
            } else {
                val = (u > 0.f) ? u : 0.f;
            }
            out[idx] = val;
        }
    }

    // (b) diagonals. Stride NP1+1 = 8194 floats; chunk = 32768 < 4*8194, so at
    // most 4 diagonal elements per matrix fall inside a chunk.
    if (tid < 8) {
        const int which = tid >> 2;  // 0 = A_low, 1 = A_up
        const size_t dbase = AB + (size_t)which * MM;
        size_t k0 = 0;
        if (s > dbase) k0 = (s - dbase + (size_t)NP1) / (size_t)(NP1 + 1);  // ceil
        const size_t k = k0 + (size_t)(tid & 3);
        const size_t p = dbase + k * (size_t)(NP1 + 1);
        if (k <= (size_t)NN && p >= s && p < e) {
            float val;
            if (k == (size_t)NN) {
                val = 1.f;
            } else {
                const int i = (int)k;
                const float l = lower[i];
                const float u = upper[i];
                const bool active   = (u > 0.f) && (l >= 0.f);
                const bool unstable = (u > 0.f) && (l < 0.f);
                if (which == 0) {
                    const float a = fminf(fmaxf(alphas[i], 0.f), 1.f);
                    val = active ? 1.f : (unstable ? a : 0.f);
                } else {
                    const float d = u - l;
                    const float lam = u / ((d == 0.f) ? 1.f : d);
                    val = active ? 1.f : (unstable ? lam : 0.f);
                }
            }
            out[p] = val;
        }
    }

    // (c) A_up last row: floats [LR0, T_TOT). cols [0,NN) = bias_up, col NN = 1.
    if (e > LR0) {
        const size_t start = (s > LR0) ? s : LR0;
        for (size_t idx = start + tid; idx < e; idx += THREADS) {
            const size_t col = idx - LR0;
            float val;
            if (col < (size_t)NN) {
                const int i = (int)col;
                const float l = lower[i];
                const float u = upper[i];
                const bool unstable = (u > 0.f) && (l < 0.f);
                const float d = u - l;
                const float lam = u / ((d == 0.f) ? 1.f : d);
                val = unstable ? (-lam * l) : 0.f;
            } else {
                val = 1.f;
            }
            out[idx] = val;
        }
    }
}

extern "C" void kernel_launch(void* const* d_in, const int* in_sizes, int n_in,
                              void* d_out, int out_size) {
    const float* lower  = (const float*)d_in[0];
    const float* upper  = (const float*)d_in[1];
    const float* alphas = (const float*)d_in[2];
    float* out = (float*)d_out;

    const int nBlocks = (int)((T_TOT + CHUNK_F - 1) / CHUNK_F);  // 4098
    relu_relax_fused<<<nBlocks, THREADS>>>(lower, upper, alphas, out);
}

// round 3
// speedup vs baseline: 1.0026x; 1.0026x over previous
#include <cuda_runtime.h>
#include <cstdint>

// Problem constants
#define NN    8192
#define NP1   8193
#define AB    16384ULL                    // A_low base (floats)
#define MM    67125249ULL                 // NP1*NP1
#define LR0   134258689ULL                // A_up last-row start (floats)
#define T_TOT 134266882ULL                // total output floats

#define THREADS  256
#define CHUNK_F  131072ULL                // floats per block = 512 KB
#define SBUF_B   32768                    // 32 KB zero buffer in SMEM

__global__ void __launch_bounds__(THREADS) relu_relax_tma(
        const float* __restrict__ lower,
        const float* __restrict__ upper,
        const float* __restrict__ alphas,
        float* __restrict__ out) {
    __shared__ alignas(128) float4 zbuf[SBUF_B / 16];

    const int tid = threadIdx.x;
    const size_t s = (size_t)blockIdx.x * CHUNK_F;
    const size_t e = (s + CHUNK_F < T_TOT) ? (s + CHUNK_F) : T_TOT;

    // ---- Zero the SMEM source tile ----
    const float4 z = make_float4(0.f, 0.f, 0.f, 0.f);
    #pragma unroll
    for (int j = tid; j < SBUF_B / 16; j += THREADS) zbuf[j] = z;
    __syncthreads();
    asm volatile("fence.proxy.async.shared::cta;" ::: "memory");

    // ---- Phase 1: TMA bulk zero-fill of this block's chunk ----
    if (tid == 0) {
        uint32_t ssrc;
        asm("{ .reg .u64 t; cvta.to.shared.u64 t, %1; cvt.u32.u64 %0, t; }"
            : "=r"(ssrc) : "l"(zbuf));
        char* g = (char*)out + s * 4;
        const size_t bytes = (e - s) * 4;
        const size_t nb16  = bytes & ~(size_t)15;   // 16B-aligned portion
        for (size_t off = 0; off < nb16; off += SBUF_B) {
            const uint32_t sz = (uint32_t)(((nb16 - off) < (size_t)SBUF_B)
                                           ? (nb16 - off) : (size_t)SBUF_B);
            asm volatile(
                "cp.async.bulk.global.shared::cta.bulk_group [%0], [%1], %2;"
                :: "l"(g + off), "r"(ssrc), "r"(sz) : "memory");
        }
        asm volatile("cp.async.bulk.commit_group;" ::: "memory");
        asm volatile("cp.async.bulk.wait_group 0;" ::: "memory");
        // Tail leftover (8 bytes in the last block) is NOT bulk-written;
        // it is covered by the last-row patch below.
    }
    __syncthreads();   // all patches ordered after this block's bulk stores

    // ---- Phase 2: patch nonzeros inside [s, e) ----

    // (a) conc_low / conc_up head: floats [0, 2*NN)  (entirely in block 0)
    if (s == 0) {
        for (int idx = tid; idx < 2 * NN; idx += THREADS) {
            const int i = idx & (NN - 1);
            const float l = lower[i];
            const float u = upper[i];
            float val;
            if (idx < NN) {
                const float a = fminf(fmaxf(alphas[i], 0.f), 1.f);
                const bool active   = (u > 0.f) && (l >= 0.f);
                const bool unstable = (u > 0.f) && (l < 0.f);
                val = active ? l : (unstable ? a * l : 0.f);
            } else {
                val = (u > 0.f) ? u : 0.f;
            }
            out[idx] = val;
        }
    }

    // (b) diagonals of A_low / A_up: p = dbase + k*(NP1+1), k in [0, NN]
    #pragma unroll
    for (int which = 0; which < 2; which++) {
        const size_t dbase = AB + (size_t)which * MM;
        size_t k0 = 0;
        if (s > dbase) k0 = (s - dbase + (size_t)NP1) / (size_t)(NP1 + 1);
        for (size_t k = k0 + (size_t)tid; k <= (size_t)NN; k += THREADS) {
            const size_t p = dbase + k * (size_t)(NP1 + 1);
            if (p >= e) break;
            if (p < s) continue;
            float val;
            if (k == (size_t)NN) {
                val = 1.f;
            } else {
                const int i = (int)k;
                const float l = lower[i];
                const float u = upper[i];
                const bool active   = (u > 0.f) && (l >= 0.f);
                const bool unstable = (u > 0.f) && (l < 0.f);
                if (which == 0) {
                    const float a = fminf(fmaxf(alphas[i], 0.f), 1.f);
                    val = active ? 1.f : (unstable ? a : 0.f);
                } else {
                    const float d = u - l;
                    const float lam = u / ((d == 0.f) ? 1.f : d);
                    val = active ? 1.f : (unstable ? lam : 0.f);
                }
            }
            out[p] = val;
        }
    }

    // (c) A_up last row: floats [LR0, T_TOT); cols [0,NN) = bias_up, col NN = 1
    if (e > LR0) {
        const size_t start = (s > LR0) ? s : LR0;
        for (size_t idx = start + tid; idx < e; idx += THREADS) {
            const size_t col = idx - LR0;
            float val;
            if (col < (size_t)NN) {
                const int i = (int)col;
                const float l = lower[i];
                const float u = upper[i];
                const bool unstable = (u > 0.f) && (l < 0.f);
                const float d = u - l;
                const float lam = u / ((d == 0.f) ? 1.f : d);
                val = unstable ? (-lam * l) : 0.f;
            } else {
                val = 1.f;
            }
            out[idx] = val;
        }
    }
}

extern "C" void kernel_launch(void* const* d_in, const int* in_sizes, int n_in,
                              void* d_out, int out_size) {
    const float* lower  = (const float*)d_in[0];
    const float* upper  = (const float*)d_in[1];
    const float* alphas = (const float*)d_in[2];
    float* out = (float*)d_out;

    const int nBlocks = (int)((T_TOT + CHUNK_F - 1) / CHUNK_F);  // 1025
    relu_relax_tma<<<nBlocks, THREADS>>>(lower, upper, alphas, out);
}